// round 5
// baseline (speedup 1.0000x reference)
#include <cuda_runtime.h>

#define NN 100000
#define EE 1600000
#define LN_EPS 1e-5f

// ---------------- scratch (static device allocations; no runtime alloc) ----------------
__device__ __align__(16) float    g_agg[NN*128];   // (1+eps)*x + sum relu(x[src]+ea)
__device__ __align__(16) float    g_h  [NN*128];   // after MLP+LN1+residual
__device__ __align__(16) float    g_xp [NN*128];   // GAT projection
__device__ __align__(16) float    g_asrc[NN*4];
__device__ __align__(16) float    g_adst[NN*4];
__device__ __align__(16) unsigned g_menc[NN*4];    // encoded segment max
__device__ __align__(16) float    g_maxf[NN*4];    // decoded segment max
__device__ __align__(16) float    g_esum[NN*4];    // segment exp-sum

// ---------------- helpers ----------------
__device__ __forceinline__ void red_add_v4(float* p, float a, float b, float c, float d) {
    asm volatile("red.global.add.v4.f32 [%0], {%1,%2,%3,%4};"
                 :: "l"(p), "f"(a), "f"(b), "f"(c), "f"(d) : "memory");
}
__device__ __forceinline__ unsigned fenc(float f) {
    unsigned u = __float_as_uint(f);
    return (u & 0x80000000u) ? ~u : (u | 0x80000000u);
}
__device__ __forceinline__ float fdec(unsigned u) {
    return (u & 0x80000000u) ? __uint_as_float(u ^ 0x80000000u) : __uint_as_float(~u);
}
__device__ __forceinline__ float lrelu(float x) { return x > 0.f ? x : 0.2f * x; }

// ---------------- K0: agg = (1+eps)*x ----------------
__global__ void k_init(const float* __restrict__ x, const float* __restrict__ eps) {
    int i = blockIdx.x * blockDim.x + threadIdx.x;           // float4 index
    float e1 = 1.0f + eps[0];
    float4 xv = ((const float4*)x)[i];
    ((float4*)g_agg)[i] = make_float4(e1*xv.x, e1*xv.y, e1*xv.z, e1*xv.w);
}

// ---------------- K1: GINE edge scatter (warp per edge) ----------------
__global__ void k_gine(const float* __restrict__ x, const int* __restrict__ ei,
                       const float* __restrict__ ea) {
    int e    = (blockIdx.x * blockDim.x + threadIdx.x) >> 5;
    int lane = threadIdx.x & 31;
    int s = __ldg(&ei[e]);
    int d = __ldg(&ei[EE + e]);
    float4 xv = __ldg(&((const float4*)x)[(size_t)s*32 + lane]);
    float4 av = __ldg(&((const float4*)ea)[(size_t)e*32 + lane]);
    float mx = fmaxf(xv.x+av.x, 0.f), my = fmaxf(xv.y+av.y, 0.f);
    float mz = fmaxf(xv.z+av.z, 0.f), mw = fmaxf(xv.w+av.w, 0.f);
    red_add_v4(&g_agg[(size_t)d*128 + lane*4], mx, my, mz, mw);
}

// ---------------- K2: fused MLP + LN1 + residual + GAT projection + logits ----------------
// 256 threads process 32 nodes/iter. thread = (q = node-quad, jq = output-quad).
// Each thread: 4 nodes x 4 outputs (register tile) -> LDS bytes/FMA ~= 2B (FMA-bound).
__device__ __forceinline__ void matvec128(float4 acc[4], const float4* __restrict__ src,
                                          const float4* __restrict__ Wv, float4 binit,
                                          int q, int jq) {
    acc[0] = binit; acc[1] = binit; acc[2] = binit; acc[3] = binit;
#pragma unroll 4
    for (int k4 = 0; k4 < 32; k4++) {
        float4 w0 = Wv[(4*k4+0)*32 + jq];
        float4 w1 = Wv[(4*k4+1)*32 + jq];
        float4 w2 = Wv[(4*k4+2)*32 + jq];
        float4 w3 = Wv[(4*k4+3)*32 + jq];
#pragma unroll
        for (int n = 0; n < 4; n++) {
            float4 xv = src[(q*4+n)*32 + k4];
            acc[n].x = fmaf(xv.w,w3.x, fmaf(xv.z,w2.x, fmaf(xv.y,w1.x, fmaf(xv.x,w0.x, acc[n].x))));
            acc[n].y = fmaf(xv.w,w3.y, fmaf(xv.z,w2.y, fmaf(xv.y,w1.y, fmaf(xv.x,w0.y, acc[n].y))));
            acc[n].z = fmaf(xv.w,w3.z, fmaf(xv.z,w2.z, fmaf(xv.y,w1.z, fmaf(xv.x,w0.z, acc[n].z))));
            acc[n].w = fmaf(xv.w,w3.w, fmaf(xv.z,w2.w, fmaf(xv.y,w1.w, fmaf(xv.x,w0.w, acc[n].w))));
        }
    }
}

__global__ void __launch_bounds__(256, 1) k_mlp(
    const float* __restrict__ x,
    const float* __restrict__ w1, const float* __restrict__ b1,
    const float* __restrict__ w2, const float* __restrict__ b2,
    const float* __restrict__ ln1g, const float* __restrict__ ln1b,
    const float* __restrict__ gw,
    const float* __restrict__ attS, const float* __restrict__ attD)
{
    extern __shared__ float sm[];
    float*  W1s = sm;            // 16384 floats
    float*  W2s = sm + 16384;
    float*  Wgs = sm + 32768;
    float4* xr4 = (float4*)(sm + 49152);        // 32 nodes x 32 float4
    float4* tr4 = (float4*)(sm + 49152 + 4096);

    for (int i = threadIdx.x; i < 4096; i += 256) {
        ((float4*)W1s)[i] = ((const float4*)w1)[i];
        ((float4*)W2s)[i] = ((const float4*)w2)[i];
        ((float4*)Wgs)[i] = ((const float4*)gw)[i];
    }
    __syncthreads();

    int q = threadIdx.x >> 5, jq = threadIdx.x & 31;
    float4 b1v = ((const float4*)b1)[jq];
    float4 b2v = ((const float4*)b2)[jq];
    float4 g1v = ((const float4*)ln1g)[jq];
    float4 e1v = ((const float4*)ln1b)[jq];
    float4 asv = ((const float4*)attS)[jq];
    float4 adv = ((const float4*)attD)[jq];
    float4 zero = make_float4(0.f, 0.f, 0.f, 0.f);

    for (int nb = blockIdx.x * 32; nb < NN; nb += gridDim.x * 32) {   // NN % 32 == 0
        for (int i = threadIdx.x; i < 1024; i += 256)
            xr4[i] = ((const float4*)g_agg)[(size_t)nb*32 + i];
        __syncthreads();

        float4 a1[4];
        matvec128(a1, xr4, (const float4*)W1s, b1v, q, jq);
#pragma unroll
        for (int n = 0; n < 4; n++) {
            a1[n].x = fmaxf(a1[n].x, 0.f); a1[n].y = fmaxf(a1[n].y, 0.f);
            a1[n].z = fmaxf(a1[n].z, 0.f); a1[n].w = fmaxf(a1[n].w, 0.f);
            tr4[(q*4+n)*32 + jq] = a1[n];
        }
        __syncthreads();

        float4 a2[4];
        matvec128(a2, tr4, (const float4*)W2s, b2v, q, jq);

        float4 hv[4];
#pragma unroll
        for (int n = 0; n < 4; n++) {
            float4 v = a2[n];
            v.x = fmaxf(v.x, 0.f); v.y = fmaxf(v.y, 0.f);
            v.z = fmaxf(v.z, 0.f); v.w = fmaxf(v.w, 0.f);
            float s  = v.x + v.y + v.z + v.w;
            float ss = v.x*v.x + v.y*v.y + v.z*v.z + v.w*v.w;
#pragma unroll
            for (int o = 16; o; o >>= 1) {
                s  += __shfl_xor_sync(0xffffffffu, s,  o);
                ss += __shfl_xor_sync(0xffffffffu, ss, o);
            }
            float mu  = s * (1.f/128.f);
            float var = ss * (1.f/128.f) - mu*mu;
            float rs  = rsqrtf(var + LN_EPS);
            int node = nb + q*4 + n;
            float4 xr = __ldg(&((const float4*)x)[(size_t)node*32 + jq]);
            float4 h;
            h.x = (v.x-mu)*rs*g1v.x + e1v.x + xr.x;
            h.y = (v.y-mu)*rs*g1v.y + e1v.y + xr.y;
            h.z = (v.z-mu)*rs*g1v.z + e1v.z + xr.z;
            h.w = (v.w-mu)*rs*g1v.w + e1v.w + xr.w;
            ((float4*)g_h)[(size_t)node*32 + jq] = h;
            hv[n] = h;
        }
        __syncthreads();
#pragma unroll
        for (int n = 0; n < 4; n++) xr4[(q*4+n)*32 + jq] = hv[n];
        __syncthreads();

        float4 a3[4];
        matvec128(a3, xr4, (const float4*)Wgs, zero, q, jq);

        float ps[4], pd[4];
#pragma unroll
        for (int n = 0; n < 4; n++) {
            int node = nb + q*4 + n;
            ((float4*)g_xp)[(size_t)node*32 + jq] = a3[n];
            ps[n] = a3[n].x*asv.x + a3[n].y*asv.y + a3[n].z*asv.z + a3[n].w*asv.w;
            pd[n] = a3[n].x*adv.x + a3[n].y*adv.y + a3[n].z*adv.z + a3[n].w*adv.w;
        }
#pragma unroll
        for (int o = 4; o; o >>= 1) {
#pragma unroll
            for (int n = 0; n < 4; n++) {
                ps[n] += __shfl_down_sync(0xffffffffu, ps[n], o);
                pd[n] += __shfl_down_sync(0xffffffffu, pd[n], o);
            }
        }
        if ((jq & 7) == 0) {
            int head = jq >> 3;
#pragma unroll
            for (int n = 0; n < 4; n++) {
                int node = nb + q*4 + n;
                g_asrc[node*4 + head] = ps[n];
                g_adst[node*4 + head] = pd[n];
                g_menc[node*4 + head] = fenc(lrelu(ps[n] + pd[n]));  // self-loop init
            }
        }
        __syncthreads();
    }
}

// ---------------- K3: per-edge segment max (thread per edge) ----------------
__global__ void k_gatmax(const int* __restrict__ ei) {
    int e = blockIdx.x * blockDim.x + threadIdx.x;
    int s = __ldg(&ei[e]);
    int d = __ldg(&ei[EE + e]);
    float4 as = __ldg(&((const float4*)g_asrc)[s]);
    float4 ad = __ldg(&((const float4*)g_adst)[d]);
    atomicMax(&g_menc[d*4 + 0], fenc(lrelu(as.x + ad.x)));
    atomicMax(&g_menc[d*4 + 1], fenc(lrelu(as.y + ad.y)));
    atomicMax(&g_menc[d*4 + 2], fenc(lrelu(as.z + ad.z)));
    atomicMax(&g_menc[d*4 + 3], fenc(lrelu(as.w + ad.w)));
}

// ---------------- K4: decode max, self-loop contribution (warp per node) ----------------
__global__ void k_selfinit(float* __restrict__ out) {
    int gt   = blockIdx.x * blockDim.x + threadIdx.x;
    int node = gt >> 5, lane = gt & 31, head = lane >> 3;
    float a  = g_asrc[node*4 + head] + g_adst[node*4 + head];
    float lg = lrelu(a);
    float mx = fdec(g_menc[node*4 + head]);
    float es = __expf(lg - mx);
    if ((lane & 7) == 0) { g_maxf[node*4 + head] = mx; g_esum[node*4 + head] = es; }
    float4 xv = ((const float4*)g_xp)[(size_t)node*32 + lane];
    ((float4*)out)[(size_t)node*32 + lane] = make_float4(es*xv.x, es*xv.y, es*xv.z, es*xv.w);
}

// ---------------- K5: GAT weighted scatter (warp per edge, unnormalized) ----------------
__global__ void k_gatagg(const int* __restrict__ ei, float* __restrict__ out) {
    int e    = (blockIdx.x * blockDim.x + threadIdx.x) >> 5;
    int lane = threadIdx.x & 31;
    int head = lane >> 3;
    int s = __ldg(&ei[e]);
    int d = __ldg(&ei[EE + e]);
    float a  = g_asrc[s*4 + head] + g_adst[d*4 + head];
    float ev = __expf(lrelu(a) - g_maxf[d*4 + head]);
    if ((lane & 7) == 0) atomicAdd(&g_esum[d*4 + head], ev);
    float4 xv = __ldg(&((const float4*)g_xp)[(size_t)s*32 + lane]);
    red_add_v4(&out[(size_t)d*128 + lane*4], ev*xv.x, ev*xv.y, ev*xv.z, ev*xv.w);
}

// ---------------- K6: normalize + bias + relu + LN2 + residual (warp per node, in-place) ----
__global__ void k_final(float* __restrict__ out, const float* __restrict__ gatb,
                        const float* __restrict__ g2, const float* __restrict__ b2l) {
    int gt   = blockIdx.x * blockDim.x + threadIdx.x;
    int node = gt >> 5, lane = gt & 31, head = lane >> 3;
    float4 ov = ((const float4*)out)[(size_t)node*32 + lane];
    float inv = 1.f / (g_esum[node*4 + head] + 1e-16f);
    float4 bb = __ldg(&((const float4*)gatb)[lane]);
    float4 v;
    v.x = fmaxf(ov.x*inv + bb.x, 0.f);
    v.y = fmaxf(ov.y*inv + bb.y, 0.f);
    v.z = fmaxf(ov.z*inv + bb.z, 0.f);
    v.w = fmaxf(ov.w*inv + bb.w, 0.f);
    float s  = v.x + v.y + v.z + v.w;
    float ss = v.x*v.x + v.y*v.y + v.z*v.z + v.w*v.w;
#pragma unroll
    for (int o = 16; o; o >>= 1) {
        s  += __shfl_xor_sync(0xffffffffu, s,  o);
        ss += __shfl_xor_sync(0xffffffffu, ss, o);
    }
    float mu  = s * (1.f/128.f);
    float var = ss * (1.f/128.f) - mu*mu;
    float rs  = rsqrtf(var + LN_EPS);
    float4 gv = __ldg(&((const float4*)g2)[lane]);
    float4 bv = __ldg(&((const float4*)b2l)[lane]);
    float4 hh = ((const float4*)g_h)[(size_t)node*32 + lane];
    float4 r;
    r.x = (v.x-mu)*rs*gv.x + bv.x + hh.x;
    r.y = (v.y-mu)*rs*gv.y + bv.y + hh.y;
    r.z = (v.z-mu)*rs*gv.z + bv.z + hh.z;
    r.w = (v.w-mu)*rs*gv.w + bv.w + hh.w;
    ((float4*)out)[(size_t)node*32 + lane] = r;
}

// ---------------- launch ----------------
extern "C" void kernel_launch(void* const* d_in, const int* in_sizes, int n_in,
                              void* d_out, int out_size) {
    const float* x   = (const float*)d_in[0];
    const int*   ei  = (const int*)  d_in[1];
    const float* ea  = (const float*)d_in[2];
    const float* eps = (const float*)d_in[3];
    const float* w1  = (const float*)d_in[4];
    const float* b1  = (const float*)d_in[5];
    const float* w2  = (const float*)d_in[6];
    const float* b2  = (const float*)d_in[7];
    const float* l1g = (const float*)d_in[8];
    const float* l1b = (const float*)d_in[9];
    const float* gw  = (const float*)d_in[10];
    const float* ats = (const float*)d_in[11];
    const float* atd = (const float*)d_in[12];
    const float* gb  = (const float*)d_in[13];
    const float* l2g = (const float*)d_in[14];
    const float* l2b = (const float*)d_in[15];
    float* out = (float*)d_out;

    cudaFuncSetAttribute(k_mlp, cudaFuncAttributeMaxDynamicSharedMemorySize, 229376);

    k_init    <<<NN*32/256, 256>>>(x, eps);                                   // 12500 blocks
    k_gine    <<<EE/8,      256>>>(x, ei, ea);                                // warp/edge
    k_mlp     <<<152, 256, 229376>>>(x, w1, b1, w2, b2, l1g, l1b, gw, ats, atd);
    k_gatmax  <<<EE/256,    256>>>(ei);
    k_selfinit<<<NN/8,      256>>>(out);
    k_gatagg  <<<EE/8,      256>>>(ei, out);
    k_final   <<<NN/8,      256>>>(out, gb, l2g, l2b);
}

// round 6
// speedup vs baseline: 1.4796x; 1.4796x over previous
#include <cuda_runtime.h>

#define NN 100000
#define EE 1600000
#define LN_EPS 1e-5f
#define SCAN_T 512
#define SCAN_BLKS ((NN + SCAN_T - 1) / SCAN_T)   // 196

// ---------------- scratch (static device allocations) ----------------
__device__ __align__(16) float g_agg[NN*128];   // (1+eps)*x + sum relu(x[src]+ea)
__device__ __align__(16) float g_h  [NN*128];   // after MLP+LN1+residual
__device__ __align__(16) float g_xp [NN*128];   // GAT projection
__device__ __align__(16) float g_asrc[NN*4];
__device__ __align__(16) float g_adst[NN*4];
__device__ int g_off [NN+1];                    // CSR offsets (by dst)
__device__ int g_cur [NN];                      // histogram / fill cursor
__device__ int g_part[SCAN_BLKS];               // scan partials
__device__ int g_csre[EE];                      // edge id sorted by dst
__device__ int g_csrs[EE];                      // src   sorted by dst

__device__ __forceinline__ float lrelu(float x) { return x > 0.f ? x : 0.2f * x; }

// ---------------- CSR build ----------------
__global__ void k_zero() {
    int i = blockIdx.x * blockDim.x + threadIdx.x;
    if (i < NN) g_cur[i] = 0;
}
__global__ void k_hist(const int* __restrict__ ei) {
    int e = blockIdx.x * blockDim.x + threadIdx.x;
    if (e < EE) atomicAdd(&g_cur[__ldg(&ei[EE + e])], 1);
}
__global__ void k_scan1() {
    __shared__ int ws[16];
    int t = threadIdx.x, b = blockIdx.x;
    int i = b * SCAN_T + t;
    int v = (i < NN) ? g_cur[i] : 0;
    int lane = t & 31, w = t >> 5;
    int s = v;
#pragma unroll
    for (int o = 1; o < 32; o <<= 1) { int n = __shfl_up_sync(0xffffffffu, s, o); if (lane >= o) s += n; }
    if (lane == 31) ws[w] = s;
    __syncthreads();
    if (w == 0) {
        int x2 = (lane < 16) ? ws[lane] : 0;
#pragma unroll
        for (int o = 1; o < 16; o <<= 1) { int n = __shfl_up_sync(0xffffffffu, x2, o); if (lane >= o) x2 += n; }
        if (lane < 16) ws[lane] = x2;
    }
    __syncthreads();
    int incl = s + (w > 0 ? ws[w-1] : 0);
    if (i < NN) g_off[i] = incl - v;             // block-local exclusive
    if (t == SCAN_T - 1) g_part[b] = incl;
}
__global__ void k_scan2() {                       // 1 block, 256 threads; SCAN_BLKS <= 256
    __shared__ int ws[8];
    int t = threadIdx.x;
    int v = (t < SCAN_BLKS) ? g_part[t] : 0;
    int lane = t & 31, w = t >> 5;
    int s = v;
#pragma unroll
    for (int o = 1; o < 32; o <<= 1) { int n = __shfl_up_sync(0xffffffffu, s, o); if (lane >= o) s += n; }
    if (lane == 31) ws[w] = s;
    __syncthreads();
    if (w == 0) {
        int x2 = (lane < 8) ? ws[lane] : 0;
#pragma unroll
        for (int o = 1; o < 8; o <<= 1) { int n = __shfl_up_sync(0xffffffffu, x2, o); if (lane >= o) x2 += n; }
        if (lane < 8) ws[lane] = x2;
    }
    __syncthreads();
    int excl = s + (w > 0 ? ws[w-1] : 0) - v;
    if (t < SCAN_BLKS) g_part[t] = excl;
}
__global__ void k_scan3() {
    int i = blockIdx.x * blockDim.x + threadIdx.x;
    if (i < NN) {
        int v = g_off[i] + g_part[i / SCAN_T];
        g_off[i] = v;
        g_cur[i] = v;
    }
    if (i == 0) g_off[NN] = EE;
}
__global__ void k_fill(const int* __restrict__ ei) {
    int e = blockIdx.x * blockDim.x + threadIdx.x;
    if (e < EE) {
        int d = __ldg(&ei[EE + e]);
        int s = __ldg(&ei[e]);
        int p = atomicAdd(&g_cur[d], 1);
        g_csre[p] = e;
        g_csrs[p] = s;
    }
}

// ---------------- K1: GINE gather (warp per node, no atomics) ----------------
__global__ void __launch_bounds__(256) k_gine_g(const float* __restrict__ x,
                                                const float* __restrict__ ea,
                                                const float* __restrict__ eps) {
    int node = blockIdx.x * 8 + (threadIdx.x >> 5);
    if (node >= NN) return;
    int lane = threadIdx.x & 31;
    int i = g_off[node], end = g_off[node + 1];
    float e1 = 1.0f + __ldg(eps);
    float4 xv = __ldg(&((const float4*)x)[(size_t)node*32 + lane]);
    float4 acc = make_float4(e1*xv.x, e1*xv.y, e1*xv.z, e1*xv.w);
    int e = 0, s = 0;
    if (i < end) { e = __ldg(&g_csre[i]); s = __ldg(&g_csrs[i]); }
    while (i < end) {
        int in = i + 1, en = 0, sn = 0;
        if (in < end) { en = __ldg(&g_csre[in]); sn = __ldg(&g_csrs[in]); }
        float4 xs = __ldg(&((const float4*)x )[(size_t)s*32 + lane]);
        float4 av = __ldg(&((const float4*)ea)[(size_t)e*32 + lane]);
        acc.x += fmaxf(xs.x + av.x, 0.f);
        acc.y += fmaxf(xs.y + av.y, 0.f);
        acc.z += fmaxf(xs.z + av.z, 0.f);
        acc.w += fmaxf(xs.w + av.w, 0.f);
        e = en; s = sn; i = in;
    }
    ((float4*)g_agg)[(size_t)node*32 + lane] = acc;
}

// ---------------- K2: fused MLP + LN1 + residual + GAT projection + logits ----------------
__device__ __forceinline__ void matvec128(float4 acc[4], const float4* __restrict__ src,
                                          const float4* __restrict__ Wv, float4 binit,
                                          int q, int jq) {
    acc[0] = binit; acc[1] = binit; acc[2] = binit; acc[3] = binit;
#pragma unroll 4
    for (int k4 = 0; k4 < 32; k4++) {
        float4 w0 = Wv[(4*k4+0)*32 + jq];
        float4 w1 = Wv[(4*k4+1)*32 + jq];
        float4 w2 = Wv[(4*k4+2)*32 + jq];
        float4 w3 = Wv[(4*k4+3)*32 + jq];
#pragma unroll
        for (int n = 0; n < 4; n++) {
            float4 xv = src[(q*4+n)*32 + k4];
            acc[n].x = fmaf(xv.w,w3.x, fmaf(xv.z,w2.x, fmaf(xv.y,w1.x, fmaf(xv.x,w0.x, acc[n].x))));
            acc[n].y = fmaf(xv.w,w3.y, fmaf(xv.z,w2.y, fmaf(xv.y,w1.y, fmaf(xv.x,w0.y, acc[n].y))));
            acc[n].z = fmaf(xv.w,w3.z, fmaf(xv.z,w2.z, fmaf(xv.y,w1.z, fmaf(xv.x,w0.z, acc[n].z))));
            acc[n].w = fmaf(xv.w,w3.w, fmaf(xv.z,w2.w, fmaf(xv.y,w1.w, fmaf(xv.x,w0.w, acc[n].w))));
        }
    }
}

__global__ void __launch_bounds__(256, 1) k_mlp(
    const float* __restrict__ x,
    const float* __restrict__ w1, const float* __restrict__ b1,
    const float* __restrict__ w2, const float* __restrict__ b2,
    const float* __restrict__ ln1g, const float* __restrict__ ln1b,
    const float* __restrict__ gw,
    const float* __restrict__ attS, const float* __restrict__ attD)
{
    extern __shared__ float sm[];
    float*  W1s = sm;
    float*  W2s = sm + 16384;
    float*  Wgs = sm + 32768;
    float4* xr4 = (float4*)(sm + 49152);
    float4* tr4 = (float4*)(sm + 49152 + 4096);

    for (int i = threadIdx.x; i < 4096; i += 256) {
        ((float4*)W1s)[i] = ((const float4*)w1)[i];
        ((float4*)W2s)[i] = ((const float4*)w2)[i];
        ((float4*)Wgs)[i] = ((const float4*)gw)[i];
    }
    __syncthreads();

    int q = threadIdx.x >> 5, jq = threadIdx.x & 31;
    float4 b1v = ((const float4*)b1)[jq];
    float4 b2v = ((const float4*)b2)[jq];
    float4 g1v = ((const float4*)ln1g)[jq];
    float4 e1v = ((const float4*)ln1b)[jq];
    float4 asv = ((const float4*)attS)[jq];
    float4 adv = ((const float4*)attD)[jq];
    float4 zero = make_float4(0.f, 0.f, 0.f, 0.f);

    for (int nb = blockIdx.x * 32; nb < NN; nb += gridDim.x * 32) {
        for (int i = threadIdx.x; i < 1024; i += 256)
            xr4[i] = ((const float4*)g_agg)[(size_t)nb*32 + i];
        __syncthreads();

        float4 a1[4];
        matvec128(a1, xr4, (const float4*)W1s, b1v, q, jq);
#pragma unroll
        for (int n = 0; n < 4; n++) {
            a1[n].x = fmaxf(a1[n].x, 0.f); a1[n].y = fmaxf(a1[n].y, 0.f);
            a1[n].z = fmaxf(a1[n].z, 0.f); a1[n].w = fmaxf(a1[n].w, 0.f);
            tr4[(q*4+n)*32 + jq] = a1[n];
        }
        __syncthreads();

        float4 a2[4];
        matvec128(a2, tr4, (const float4*)W2s, b2v, q, jq);

        float4 hv[4];
#pragma unroll
        for (int n = 0; n < 4; n++) {
            float4 v = a2[n];
            v.x = fmaxf(v.x, 0.f); v.y = fmaxf(v.y, 0.f);
            v.z = fmaxf(v.z, 0.f); v.w = fmaxf(v.w, 0.f);
            float s  = v.x + v.y + v.z + v.w;
            float ss = v.x*v.x + v.y*v.y + v.z*v.z + v.w*v.w;
#pragma unroll
            for (int o = 16; o; o >>= 1) {
                s  += __shfl_xor_sync(0xffffffffu, s,  o);
                ss += __shfl_xor_sync(0xffffffffu, ss, o);
            }
            float mu  = s * (1.f/128.f);
            float var = ss * (1.f/128.f) - mu*mu;
            float rs  = rsqrtf(var + LN_EPS);
            int node = nb + q*4 + n;
            float4 xr = __ldg(&((const float4*)x)[(size_t)node*32 + jq]);
            float4 h;
            h.x = (v.x-mu)*rs*g1v.x + e1v.x + xr.x;
            h.y = (v.y-mu)*rs*g1v.y + e1v.y + xr.y;
            h.z = (v.z-mu)*rs*g1v.z + e1v.z + xr.z;
            h.w = (v.w-mu)*rs*g1v.w + e1v.w + xr.w;
            ((float4*)g_h)[(size_t)node*32 + jq] = h;
            hv[n] = h;
        }
        __syncthreads();
#pragma unroll
        for (int n = 0; n < 4; n++) xr4[(q*4+n)*32 + jq] = hv[n];
        __syncthreads();

        float4 a3[4];
        matvec128(a3, xr4, (const float4*)Wgs, zero, q, jq);

        float ps[4], pd[4];
#pragma unroll
        for (int n = 0; n < 4; n++) {
            int node = nb + q*4 + n;
            ((float4*)g_xp)[(size_t)node*32 + jq] = a3[n];
            ps[n] = a3[n].x*asv.x + a3[n].y*asv.y + a3[n].z*asv.z + a3[n].w*asv.w;
            pd[n] = a3[n].x*adv.x + a3[n].y*adv.y + a3[n].z*adv.z + a3[n].w*adv.w;
        }
#pragma unroll
        for (int o = 4; o; o >>= 1) {
#pragma unroll
            for (int n = 0; n < 4; n++) {
                ps[n] += __shfl_down_sync(0xffffffffu, ps[n], o);
                pd[n] += __shfl_down_sync(0xffffffffu, pd[n], o);
            }
        }
        if ((jq & 7) == 0) {
            int head = jq >> 3;
#pragma unroll
            for (int n = 0; n < 4; n++) {
                int node = nb + q*4 + n;
                g_asrc[node*4 + head] = ps[n];
                g_adst[node*4 + head] = pd[n];
            }
        }
        __syncthreads();
    }
}

// ---------------- K3: fused GAT online-softmax gather + LN2 + residual ----------------
__global__ void __launch_bounds__(256) k_gat_g(const float* __restrict__ gatb,
                                               const float* __restrict__ g2,
                                               const float* __restrict__ b2l,
                                               float* __restrict__ out) {
    int node = blockIdx.x * 8 + (threadIdx.x >> 5);
    if (node >= NN) return;
    int lane = threadIdx.x & 31, head = lane >> 3;
    int i = g_off[node], end = g_off[node + 1];

    float adst = g_adst[node*4 + head];
    float m = lrelu(g_asrc[node*4 + head] + adst);     // self-loop logit
    float sum = 1.0f;                                   // exp(self - m) = 1
    float4 acc = ((const float4*)g_xp)[(size_t)node*32 + lane];

    int s = 0;
    if (i < end) s = __ldg(&g_csrs[i]);
    while (i < end) {
        int in = i + 1, sn = 0;
        if (in < end) sn = __ldg(&g_csrs[in]);
        float lg = lrelu(__ldg(&g_asrc[s*4 + head]) + adst);
        float4 xs = __ldg(&((const float4*)g_xp)[(size_t)s*32 + lane]);
        float ev;
        if (lg > m) {
            float sc = __expf(m - lg);
            sum *= sc;
            acc.x *= sc; acc.y *= sc; acc.z *= sc; acc.w *= sc;
            m = lg; ev = 1.0f;
        } else {
            ev = __expf(lg - m);
        }
        sum += ev;
        acc.x = fmaf(ev, xs.x, acc.x);
        acc.y = fmaf(ev, xs.y, acc.y);
        acc.z = fmaf(ev, xs.z, acc.z);
        acc.w = fmaf(ev, xs.w, acc.w);
        s = sn; i = in;
    }

    float inv = 1.0f / (sum + 1e-16f);
    float4 bb = __ldg(&((const float4*)gatb)[lane]);
    float4 v;
    v.x = fmaxf(fmaf(acc.x, inv, bb.x), 0.f);
    v.y = fmaxf(fmaf(acc.y, inv, bb.y), 0.f);
    v.z = fmaxf(fmaf(acc.z, inv, bb.z), 0.f);
    v.w = fmaxf(fmaf(acc.w, inv, bb.w), 0.f);
    float sv  = v.x + v.y + v.z + v.w;
    float ssv = v.x*v.x + v.y*v.y + v.z*v.z + v.w*v.w;
#pragma unroll
    for (int o = 16; o; o >>= 1) {
        sv  += __shfl_xor_sync(0xffffffffu, sv,  o);
        ssv += __shfl_xor_sync(0xffffffffu, ssv, o);
    }
    float mu  = sv * (1.f/128.f);
    float var = ssv * (1.f/128.f) - mu*mu;
    float rs  = rsqrtf(var + LN_EPS);
    float4 gv = __ldg(&((const float4*)g2)[lane]);
    float4 bv = __ldg(&((const float4*)b2l)[lane]);
    float4 hh = ((const float4*)g_h)[(size_t)node*32 + lane];
    float4 r;
    r.x = (v.x-mu)*rs*gv.x + bv.x + hh.x;
    r.y = (v.y-mu)*rs*gv.y + bv.y + hh.y;
    r.z = (v.z-mu)*rs*gv.z + bv.z + hh.z;
    r.w = (v.w-mu)*rs*gv.w + bv.w + hh.w;
    ((float4*)out)[(size_t)node*32 + lane] = r;
}

// ---------------- launch ----------------
extern "C" void kernel_launch(void* const* d_in, const int* in_sizes, int n_in,
                              void* d_out, int out_size) {
    const float* x   = (const float*)d_in[0];
    const int*   ei  = (const int*)  d_in[1];
    const float* ea  = (const float*)d_in[2];
    const float* eps = (const float*)d_in[3];
    const float* w1  = (const float*)d_in[4];
    const float* b1  = (const float*)d_in[5];
    const float* w2  = (const float*)d_in[6];
    const float* b2  = (const float*)d_in[7];
    const float* l1g = (const float*)d_in[8];
    const float* l1b = (const float*)d_in[9];
    const float* gw  = (const float*)d_in[10];
    const float* ats = (const float*)d_in[11];
    const float* atd = (const float*)d_in[12];
    const float* gb  = (const float*)d_in[13];
    const float* l2g = (const float*)d_in[14];
    const float* l2b = (const float*)d_in[15];
    float* out = (float*)d_out;

    cudaFuncSetAttribute(k_mlp, cudaFuncAttributeMaxDynamicSharedMemorySize, 229376);

    // CSR build (by dst)
    k_zero <<<(NN + 255)/256, 256>>>();
    k_hist <<<(EE + 255)/256, 256>>>(ei);
    k_scan1<<<SCAN_BLKS, SCAN_T>>>();
    k_scan2<<<1, 256>>>();
    k_scan3<<<(NN + 255)/256, 256>>>();
    k_fill <<<(EE + 255)/256, 256>>>(ei);

    // main pipeline (gather-based, atomic-free)
    k_gine_g<<<(NN + 7)/8, 256>>>(x, ea, eps);
    k_mlp   <<<152, 256, 229376>>>(x, w1, b1, w2, b2, l1g, l1b, gw, ats, atd);
    k_gat_g <<<(NN + 7)/8, 256>>>(gb, l2g, l2b, out);
}

// round 7
// speedup vs baseline: 1.4803x; 1.0005x over previous
#include <cuda_runtime.h>

#define NN 100000
#define EE 1600000
#define LN_EPS 1e-5f
#define SCAN_T 512
#define SCAN_BLKS ((NN + SCAN_T - 1) / SCAN_T)   // 196

// ---------------- scratch (static device allocations) ----------------
__device__ __align__(16) float g_agg[NN*128];   // (1+eps)*x + sum relu(x[src]+ea)
__device__ __align__(16) float g_h  [NN*128];   // after MLP+LN1+residual
__device__ __align__(16) float g_xp [NN*128];   // GAT projection
__device__ __align__(16) float g_asrc[NN*4];
__device__ __align__(16) float g_adst[NN*4];
__device__ int g_off [NN+1];                    // CSR offsets (by dst)
__device__ int g_cur [NN];                      // histogram / fill cursor
__device__ int g_part[SCAN_BLKS];               // scan partials
__device__ int g_csre[EE];                      // edge id sorted by dst
__device__ int g_csrs[EE];                      // src   sorted by dst

__device__ __forceinline__ float lrelu(float x) { return x > 0.f ? x : 0.2f * x; }

// ---------------- CSR build ----------------
__global__ void k_zero() {
    int i = blockIdx.x * blockDim.x + threadIdx.x;
    if (i < NN) g_cur[i] = 0;
}
__global__ void k_hist(const int* __restrict__ ei) {
    int e = blockIdx.x * blockDim.x + threadIdx.x;
    if (e < EE) atomicAdd(&g_cur[__ldg(&ei[EE + e])], 1);
}
__global__ void k_scan1() {
    __shared__ int ws[16];
    int t = threadIdx.x, b = blockIdx.x;
    int i = b * SCAN_T + t;
    int v = (i < NN) ? g_cur[i] : 0;
    int lane = t & 31, w = t >> 5;
    int s = v;
#pragma unroll
    for (int o = 1; o < 32; o <<= 1) { int n = __shfl_up_sync(0xffffffffu, s, o); if (lane >= o) s += n; }
    if (lane == 31) ws[w] = s;
    __syncthreads();
    if (w == 0) {
        int x2 = (lane < 16) ? ws[lane] : 0;
#pragma unroll
        for (int o = 1; o < 16; o <<= 1) { int n = __shfl_up_sync(0xffffffffu, x2, o); if (lane >= o) x2 += n; }
        if (lane < 16) ws[lane] = x2;
    }
    __syncthreads();
    int incl = s + (w > 0 ? ws[w-1] : 0);
    if (i < NN) g_off[i] = incl - v;             // block-local exclusive
    if (t == SCAN_T - 1) g_part[b] = incl;
}
__global__ void k_scan2() {                       // 1 block, 256 threads; SCAN_BLKS <= 256
    __shared__ int ws[8];
    int t = threadIdx.x;
    int v = (t < SCAN_BLKS) ? g_part[t] : 0;
    int lane = t & 31, w = t >> 5;
    int s = v;
#pragma unroll
    for (int o = 1; o < 32; o <<= 1) { int n = __shfl_up_sync(0xffffffffu, s, o); if (lane >= o) s += n; }
    if (lane == 31) ws[w] = s;
    __syncthreads();
    if (w == 0) {
        int x2 = (lane < 8) ? ws[lane] : 0;
#pragma unroll
        for (int o = 1; o < 8; o <<= 1) { int n = __shfl_up_sync(0xffffffffu, x2, o); if (lane >= o) x2 += n; }
        if (lane < 8) ws[lane] = x2;
    }
    __syncthreads();
    int excl = s + (w > 0 ? ws[w-1] : 0) - v;
    if (t < SCAN_BLKS) g_part[t] = excl;
}
__global__ void k_scan3() {
    int i = blockIdx.x * blockDim.x + threadIdx.x;
    if (i < NN) {
        int v = g_off[i] + g_part[i / SCAN_T];
        g_off[i] = v;
        g_cur[i] = v;
    }
    if (i == 0) g_off[NN] = EE;
}
__global__ void k_fill(const int* __restrict__ ei) {
    int e = blockIdx.x * blockDim.x + threadIdx.x;
    if (e < EE) {
        int d = __ldg(&ei[EE + e]);
        int s = __ldg(&ei[e]);
        int p = atomicAdd(&g_cur[d], 1);
        g_csre[p] = e;
        g_csrs[p] = s;
    }
}

// ---------------- K1: GINE gather (warp per node, no atomics) ----------------
__global__ void __launch_bounds__(256) k_gine_g(const float* __restrict__ x,
                                                const float* __restrict__ ea,
                                                const float* __restrict__ eps) {
    int node = blockIdx.x * 8 + (threadIdx.x >> 5);
    if (node >= NN) return;
    int lane = threadIdx.x & 31;
    int i = g_off[node], end = g_off[node + 1];
    float e1 = 1.0f + __ldg(eps);
    float4 xv = __ldg(&((const float4*)x)[(size_t)node*32 + lane]);
    float4 acc = make_float4(e1*xv.x, e1*xv.y, e1*xv.z, e1*xv.w);
    int e = 0, s = 0;
    if (i < end) { e = __ldg(&g_csre[i]); s = __ldg(&g_csrs[i]); }
    while (i < end) {
        int in = i + 1, en = 0, sn = 0;
        if (in < end) { en = __ldg(&g_csre[in]); sn = __ldg(&g_csrs[in]); }
        float4 xs = __ldg(&((const float4*)x )[(size_t)s*32 + lane]);
        float4 av = __ldg(&((const float4*)ea)[(size_t)e*32 + lane]);
        acc.x += fmaxf(xs.x + av.x, 0.f);
        acc.y += fmaxf(xs.y + av.y, 0.f);
        acc.z += fmaxf(xs.z + av.z, 0.f);
        acc.w += fmaxf(xs.w + av.w, 0.f);
        e = en; s = sn; i = in;
    }
    ((float4*)g_agg)[(size_t)node*32 + lane] = acc;
}

// ---------------- K2: fused MLP + LN1 + residual + GAT projection + logits ----------------
__device__ __forceinline__ void matvec128(float4 acc[4], const float4* __restrict__ src,
                                          const float4* __restrict__ Wv, float4 binit,
                                          int q, int jq) {
    acc[0] = binit; acc[1] = binit; acc[2] = binit; acc[3] = binit;
#pragma unroll 4
    for (int k4 = 0; k4 < 32; k4++) {
        float4 w0 = Wv[(4*k4+0)*32 + jq];
        float4 w1 = Wv[(4*k4+1)*32 + jq];
        float4 w2 = Wv[(4*k4+2)*32 + jq];
        float4 w3 = Wv[(4*k4+3)*32 + jq];
#pragma unroll
        for (int n = 0; n < 4; n++) {
            float4 xv = src[(q*4+n)*32 + k4];
            acc[n].x = fmaf(xv.w,w3.x, fmaf(xv.z,w2.x, fmaf(xv.y,w1.x, fmaf(xv.x,w0.x, acc[n].x))));
            acc[n].y = fmaf(xv.w,w3.y, fmaf(xv.z,w2.y, fmaf(xv.y,w1.y, fmaf(xv.x,w0.y, acc[n].y))));
            acc[n].z = fmaf(xv.w,w3.z, fmaf(xv.z,w2.z, fmaf(xv.y,w1.z, fmaf(xv.x,w0.z, acc[n].z))));
            acc[n].w = fmaf(xv.w,w3.w, fmaf(xv.z,w2.w, fmaf(xv.y,w1.w, fmaf(xv.x,w0.w, acc[n].w))));
        }
    }
}

__global__ void __launch_bounds__(256, 1) k_mlp(
    const float* __restrict__ x,
    const float* __restrict__ w1, const float* __restrict__ b1,
    const float* __restrict__ w2, const float* __restrict__ b2,
    const float* __restrict__ ln1g, const float* __restrict__ ln1b,
    const float* __restrict__ gw,
    const float* __restrict__ attS, const float* __restrict__ attD)
{
    extern __shared__ float sm[];
    float*  W1s = sm;
    float*  W2s = sm + 16384;
    float*  Wgs = sm + 32768;
    float4* xr4 = (float4*)(sm + 49152);
    float4* tr4 = (float4*)(sm + 49152 + 4096);

    for (int i = threadIdx.x; i < 4096; i += 256) {
        ((float4*)W1s)[i] = ((const float4*)w1)[i];
        ((float4*)W2s)[i] = ((const float4*)w2)[i];
        ((float4*)Wgs)[i] = ((const float4*)gw)[i];
    }
    __syncthreads();

    int q = threadIdx.x >> 5, jq = threadIdx.x & 31;
    float4 b1v = ((const float4*)b1)[jq];
    float4 b2v = ((const float4*)b2)[jq];
    float4 g1v = ((const float4*)ln1g)[jq];
    float4 e1v = ((const float4*)ln1b)[jq];
    float4 asv = ((const float4*)attS)[jq];
    float4 adv = ((const float4*)attD)[jq];
    float4 zero = make_float4(0.f, 0.f, 0.f, 0.f);

    for (int nb = blockIdx.x * 32; nb < NN; nb += gridDim.x * 32) {
        for (int i = threadIdx.x; i < 1024; i += 256)
            xr4[i] = ((const float4*)g_agg)[(size_t)nb*32 + i];
        __syncthreads();

        float4 a1[4];
        matvec128(a1, xr4, (const float4*)W1s, b1v, q, jq);
#pragma unroll
        for (int n = 0; n < 4; n++) {
            a1[n].x = fmaxf(a1[n].x, 0.f); a1[n].y = fmaxf(a1[n].y, 0.f);
            a1[n].z = fmaxf(a1[n].z, 0.f); a1[n].w = fmaxf(a1[n].w, 0.f);
            tr4[(q*4+n)*32 + jq] = a1[n];
        }
        __syncthreads();

        float4 a2[4];
        matvec128(a2, tr4, (const float4*)W2s, b2v, q, jq);

        float4 hv[4];
#pragma unroll
        for (int n = 0; n < 4; n++) {
            float4 v = a2[n];
            v.x = fmaxf(v.x, 0.f); v.y = fmaxf(v.y, 0.f);
            v.z = fmaxf(v.z, 0.f); v.w = fmaxf(v.w, 0.f);
            float s  = v.x + v.y + v.z + v.w;
            float ss = v.x*v.x + v.y*v.y + v.z*v.z + v.w*v.w;
#pragma unroll
            for (int o = 16; o; o >>= 1) {
                s  += __shfl_xor_sync(0xffffffffu, s,  o);
                ss += __shfl_xor_sync(0xffffffffu, ss, o);
            }
            float mu  = s * (1.f/128.f);
            float var = ss * (1.f/128.f) - mu*mu;
            float rs  = rsqrtf(var + LN_EPS);
            int node = nb + q*4 + n;
            float4 xr = __ldg(&((const float4*)x)[(size_t)node*32 + jq]);
            float4 h;
            h.x = (v.x-mu)*rs*g1v.x + e1v.x + xr.x;
            h.y = (v.y-mu)*rs*g1v.y + e1v.y + xr.y;
            h.z = (v.z-mu)*rs*g1v.z + e1v.z + xr.z;
            h.w = (v.w-mu)*rs*g1v.w + e1v.w + xr.w;
            ((float4*)g_h)[(size_t)node*32 + jq] = h;
            hv[n] = h;
        }
        __syncthreads();
#pragma unroll
        for (int n = 0; n < 4; n++) xr4[(q*4+n)*32 + jq] = hv[n];
        __syncthreads();

        float4 a3[4];
        matvec128(a3, xr4, (const float4*)Wgs, zero, q, jq);

        float ps[4], pd[4];
#pragma unroll
        for (int n = 0; n < 4; n++) {
            int node = nb + q*4 + n;
            ((float4*)g_xp)[(size_t)node*32 + jq] = a3[n];
            ps[n] = a3[n].x*asv.x + a3[n].y*asv.y + a3[n].z*asv.z + a3[n].w*asv.w;
            pd[n] = a3[n].x*adv.x + a3[n].y*adv.y + a3[n].z*adv.z + a3[n].w*adv.w;
        }
#pragma unroll
        for (int o = 4; o; o >>= 1) {
#pragma unroll
            for (int n = 0; n < 4; n++) {
                ps[n] += __shfl_down_sync(0xffffffffu, ps[n], o);
                pd[n] += __shfl_down_sync(0xffffffffu, pd[n], o);
            }
        }
        if ((jq & 7) == 0) {
            int head = jq >> 3;
#pragma unroll
            for (int n = 0; n < 4; n++) {
                int node = nb + q*4 + n;
                g_asrc[node*4 + head] = ps[n];
                g_adst[node*4 + head] = pd[n];
            }
        }
        __syncthreads();
    }
}

// ---------------- K3: fused GAT online-softmax gather + LN2 + residual ----------------
__global__ void __launch_bounds__(256) k_gat_g(const float* __restrict__ gatb,
                                               const float* __restrict__ g2,
                                               const float* __restrict__ b2l,
                                               float* __restrict__ out) {
    int node = blockIdx.x * 8 + (threadIdx.x >> 5);
    if (node >= NN) return;
    int lane = threadIdx.x & 31, head = lane >> 3;
    int i = g_off[node], end = g_off[node + 1];

    float adst = g_adst[node*4 + head];
    float m = lrelu(g_asrc[node*4 + head] + adst);     // self-loop logit
    float sum = 1.0f;                                   // exp(self - m) = 1
    float4 acc = ((const float4*)g_xp)[(size_t)node*32 + lane];

    int s = 0;
    if (i < end) s = __ldg(&g_csrs[i]);
    while (i < end) {
        int in = i + 1, sn = 0;
        if (in < end) sn = __ldg(&g_csrs[in]);
        float lg = lrelu(__ldg(&g_asrc[s*4 + head]) + adst);
        float4 xs = __ldg(&((const float4*)g_xp)[(size_t)s*32 + lane]);
        float ev;
        if (lg > m) {
            float sc = __expf(m - lg);
            sum *= sc;
            acc.x *= sc; acc.y *= sc; acc.z *= sc; acc.w *= sc;
            m = lg; ev = 1.0f;
        } else {
            ev = __expf(lg - m);
        }
        sum += ev;
        acc.x = fmaf(ev, xs.x, acc.x);
        acc.y = fmaf(ev, xs.y, acc.y);
        acc.z = fmaf(ev, xs.z, acc.z);
        acc.w = fmaf(ev, xs.w, acc.w);
        s = sn; i = in;
    }

    float inv = 1.0f / (sum + 1e-16f);
    float4 bb = __ldg(&((const float4*)gatb)[lane]);
    float4 v;
    v.x = fmaxf(fmaf(acc.x, inv, bb.x), 0.f);
    v.y = fmaxf(fmaf(acc.y, inv, bb.y), 0.f);
    v.z = fmaxf(fmaf(acc.z, inv, bb.z), 0.f);
    v.w = fmaxf(fmaf(acc.w, inv, bb.w), 0.f);
    float sv  = v.x + v.y + v.z + v.w;
    float ssv = v.x*v.x + v.y*v.y + v.z*v.z + v.w*v.w;
#pragma unroll
    for (int o = 16; o; o >>= 1) {
        sv  += __shfl_xor_sync(0xffffffffu, sv,  o);
        ssv += __shfl_xor_sync(0xffffffffu, ssv, o);
    }
    float mu  = sv * (1.f/128.f);
    float var = ssv * (1.f/128.f) - mu*mu;
    float rs  = rsqrtf(var + LN_EPS);
    float4 gv = __ldg(&((const float4*)g2)[lane]);
    float4 bv = __ldg(&((const float4*)b2l)[lane]);
    float4 hh = ((const float4*)g_h)[(size_t)node*32 + lane];
    float4 r;
    r.x = (v.x-mu)*rs*gv.x + bv.x + hh.x;
    r.y = (v.y-mu)*rs*gv.y + bv.y + hh.y;
    r.z = (v.z-mu)*rs*gv.z + bv.z + hh.z;
    r.w = (v.w-mu)*rs*gv.w + bv.w + hh.w;
    ((float4*)out)[(size_t)node*32 + lane] = r;
}

// ---------------- launch ----------------
extern "C" void kernel_launch(void* const* d_in, const int* in_sizes, int n_in,
                              void* d_out, int out_size) {
    const float* x   = (const float*)d_in[0];
    const int*   ei  = (const int*)  d_in[1];
    const float* ea  = (const float*)d_in[2];
    const float* eps = (const float*)d_in[3];
    const float* w1  = (const float*)d_in[4];
    const float* b1  = (const float*)d_in[5];
    const float* w2  = (const float*)d_in[6];
    const float* b2  = (const float*)d_in[7];
    const float* l1g = (const float*)d_in[8];
    const float* l1b = (const float*)d_in[9];
    const float* gw  = (const float*)d_in[10];
    const float* ats = (const float*)d_in[11];
    const float* atd = (const float*)d_in[12];
    const float* gb  = (const float*)d_in[13];
    const float* l2g = (const float*)d_in[14];
    const float* l2b = (const float*)d_in[15];
    float* out = (float*)d_out;

    cudaFuncSetAttribute(k_mlp, cudaFuncAttributeMaxDynamicSharedMemorySize, 229376);

    // CSR build (by dst)
    k_zero <<<(NN + 255)/256, 256>>>();
    k_hist <<<(EE + 255)/256, 256>>>(ei);
    k_scan1<<<SCAN_BLKS, SCAN_T>>>();
    k_scan2<<<1, 256>>>();
    k_scan3<<<(NN + 255)/256, 256>>>();
    k_fill <<<(EE + 255)/256, 256>>>(ei);

    // main pipeline (gather-based, atomic-free)
    k_gine_g<<<(NN + 7)/8, 256>>>(x, ea, eps);
    k_mlp   <<<152, 256, 229376>>>(x, w1, b1, w2, b2, l1g, l1b, gw, ats, atd);
    k_gat_g <<<(NN + 7)/8, 256>>>(gb, l2g, l2b, out);
}

// round 8
// speedup vs baseline: 1.4804x; 1.0001x over previous
#include <cuda_runtime.h>

#define NN 100000
#define EE 1600000
#define LN_EPS 1e-5f
#define SCAN_T 512
#define SCAN_BLKS ((NN + SCAN_T - 1) / SCAN_T)   // 196

// ---------------- scratch (static device allocations) ----------------
__device__ __align__(16) float g_agg[NN*128];   // (1+eps)*x + sum relu(x[src]+ea)
__device__ __align__(16) float g_h  [NN*128];   // after MLP+LN1+residual
__device__ __align__(16) float g_xp [NN*128];   // GAT projection
__device__ __align__(16) float g_asrc[NN*4];
__device__ __align__(16) float g_adst[NN*4];
__device__ int g_off [NN+1];                    // CSR offsets (by dst)
__device__ int g_cur [NN];                      // histogram / fill cursor
__device__ int g_part[SCAN_BLKS];               // scan partials
__device__ int g_csre[EE];                      // edge id sorted by dst
__device__ int g_csrs[EE];                      // src   sorted by dst

__device__ __forceinline__ float lrelu(float x) { return x > 0.f ? x : 0.2f * x; }

// ---------------- CSR build ----------------
__global__ void k_zero() {
    int i = blockIdx.x * blockDim.x + threadIdx.x;
    if (i < NN) g_cur[i] = 0;
}
__global__ void k_hist(const int* __restrict__ ei) {
    int e = blockIdx.x * blockDim.x + threadIdx.x;
    if (e < EE) atomicAdd(&g_cur[__ldg(&ei[EE + e])], 1);
}
__global__ void k_scan1() {
    __shared__ int ws[16];
    int t = threadIdx.x, b = blockIdx.x;
    int i = b * SCAN_T + t;
    int v = (i < NN) ? g_cur[i] : 0;
    int lane = t & 31, w = t >> 5;
    int s = v;
#pragma unroll
    for (int o = 1; o < 32; o <<= 1) { int n = __shfl_up_sync(0xffffffffu, s, o); if (lane >= o) s += n; }
    if (lane == 31) ws[w] = s;
    __syncthreads();
    if (w == 0) {
        int x2 = (lane < 16) ? ws[lane] : 0;
#pragma unroll
        for (int o = 1; o < 16; o <<= 1) { int n = __shfl_up_sync(0xffffffffu, x2, o); if (lane >= o) x2 += n; }
        if (lane < 16) ws[lane] = x2;
    }
    __syncthreads();
    int incl = s + (w > 0 ? ws[w-1] : 0);
    if (i < NN) g_off[i] = incl - v;             // block-local exclusive
    if (t == SCAN_T - 1) g_part[b] = incl;
}
__global__ void k_scan2() {                       // 1 block, 256 threads; SCAN_BLKS <= 256
    __shared__ int ws[8];
    int t = threadIdx.x;
    int v = (t < SCAN_BLKS) ? g_part[t] : 0;
    int lane = t & 31, w = t >> 5;
    int s = v;
#pragma unroll
    for (int o = 1; o < 32; o <<= 1) { int n = __shfl_up_sync(0xffffffffu, s, o); if (lane >= o) s += n; }
    if (lane == 31) ws[w] = s;
    __syncthreads();
    if (w == 0) {
        int x2 = (lane < 8) ? ws[lane] : 0;
#pragma unroll
        for (int o = 1; o < 8; o <<= 1) { int n = __shfl_up_sync(0xffffffffu, x2, o); if (lane >= o) x2 += n; }
        if (lane < 8) ws[lane] = x2;
    }
    __syncthreads();
    int excl = s + (w > 0 ? ws[w-1] : 0) - v;
    if (t < SCAN_BLKS) g_part[t] = excl;
}
__global__ void k_scan3() {
    int i = blockIdx.x * blockDim.x + threadIdx.x;
    if (i < NN) {
        int v = g_off[i] + g_part[i / SCAN_T];
        g_off[i] = v;
        g_cur[i] = v;
    }
    if (i == 0) g_off[NN] = EE;
}
__global__ void k_fill(const int* __restrict__ ei) {
    int e = blockIdx.x * blockDim.x + threadIdx.x;
    if (e < EE) {
        int d = __ldg(&ei[EE + e]);
        int s = __ldg(&ei[e]);
        int p = atomicAdd(&g_cur[d], 1);
        g_csre[p] = e;
        g_csrs[p] = s;
    }
}

// ---------------- K1: GINE gather (warp per node, no atomics) ----------------
__global__ void __launch_bounds__(256) k_gine_g(const float* __restrict__ x,
                                                const float* __restrict__ ea,
                                                const float* __restrict__ eps) {
    int node = blockIdx.x * 8 + (threadIdx.x >> 5);
    if (node >= NN) return;
    int lane = threadIdx.x & 31;
    int i = g_off[node], end = g_off[node + 1];
    float e1 = 1.0f + __ldg(eps);
    float4 xv = __ldg(&((const float4*)x)[(size_t)node*32 + lane]);
    float4 acc = make_float4(e1*xv.x, e1*xv.y, e1*xv.z, e1*xv.w);
    int e = 0, s = 0;
    if (i < end) { e = __ldg(&g_csre[i]); s = __ldg(&g_csrs[i]); }
    while (i < end) {
        int in = i + 1, en = 0, sn = 0;
        if (in < end) { en = __ldg(&g_csre[in]); sn = __ldg(&g_csrs[in]); }
        float4 xs = __ldg(&((const float4*)x )[(size_t)s*32 + lane]);
        float4 av = __ldg(&((const float4*)ea)[(size_t)e*32 + lane]);
        acc.x += fmaxf(xs.x + av.x, 0.f);
        acc.y += fmaxf(xs.y + av.y, 0.f);
        acc.z += fmaxf(xs.z + av.z, 0.f);
        acc.w += fmaxf(xs.w + av.w, 0.f);
        e = en; s = sn; i = in;
    }
    ((float4*)g_agg)[(size_t)node*32 + lane] = acc;
}

// ---------------- K2: fused MLP + LN1 + residual + GAT projection + logits ----------------
__device__ __forceinline__ void matvec128(float4 acc[4], const float4* __restrict__ src,
                                          const float4* __restrict__ Wv, float4 binit,
                                          int q, int jq) {
    acc[0] = binit; acc[1] = binit; acc[2] = binit; acc[3] = binit;
#pragma unroll 4
    for (int k4 = 0; k4 < 32; k4++) {
        float4 w0 = Wv[(4*k4+0)*32 + jq];
        float4 w1 = Wv[(4*k4+1)*32 + jq];
        float4 w2 = Wv[(4*k4+2)*32 + jq];
        float4 w3 = Wv[(4*k4+3)*32 + jq];
#pragma unroll
        for (int n = 0; n < 4; n++) {
            float4 xv = src[(q*4+n)*32 + k4];
            acc[n].x = fmaf(xv.w,w3.x, fmaf(xv.z,w2.x, fmaf(xv.y,w1.x, fmaf(xv.x,w0.x, acc[n].x))));
            acc[n].y = fmaf(xv.w,w3.y, fmaf(xv.z,w2.y, fmaf(xv.y,w1.y, fmaf(xv.x,w0.y, acc[n].y))));
            acc[n].z = fmaf(xv.w,w3.z, fmaf(xv.z,w2.z, fmaf(xv.y,w1.z, fmaf(xv.x,w0.z, acc[n].z))));
            acc[n].w = fmaf(xv.w,w3.w, fmaf(xv.z,w2.w, fmaf(xv.y,w1.w, fmaf(xv.x,w0.w, acc[n].w))));
        }
    }
}

__global__ void __launch_bounds__(256, 1) k_mlp(
    const float* __restrict__ x,
    const float* __restrict__ w1, const float* __restrict__ b1,
    const float* __restrict__ w2, const float* __restrict__ b2,
    const float* __restrict__ ln1g, const float* __restrict__ ln1b,
    const float* __restrict__ gw,
    const float* __restrict__ attS, const float* __restrict__ attD)
{
    extern __shared__ float sm[];
    float*  W1s = sm;
    float*  W2s = sm + 16384;
    float*  Wgs = sm + 32768;
    float4* xr4 = (float4*)(sm + 49152);
    float4* tr4 = (float4*)(sm + 49152 + 4096);

    for (int i = threadIdx.x; i < 4096; i += 256) {
        ((float4*)W1s)[i] = ((const float4*)w1)[i];
        ((float4*)W2s)[i] = ((const float4*)w2)[i];
        ((float4*)Wgs)[i] = ((const float4*)gw)[i];
    }
    __syncthreads();

    int q = threadIdx.x >> 5, jq = threadIdx.x & 31;
    float4 b1v = ((const float4*)b1)[jq];
    float4 b2v = ((const float4*)b2)[jq];
    float4 g1v = ((const float4*)ln1g)[jq];
    float4 e1v = ((const float4*)ln1b)[jq];
    float4 asv = ((const float4*)attS)[jq];
    float4 adv = ((const float4*)attD)[jq];
    float4 zero = make_float4(0.f, 0.f, 0.f, 0.f);

    for (int nb = blockIdx.x * 32; nb < NN; nb += gridDim.x * 32) {
        for (int i = threadIdx.x; i < 1024; i += 256)
            xr4[i] = ((const float4*)g_agg)[(size_t)nb*32 + i];
        __syncthreads();

        float4 a1[4];
        matvec128(a1, xr4, (const float4*)W1s, b1v, q, jq);
#pragma unroll
        for (int n = 0; n < 4; n++) {
            a1[n].x = fmaxf(a1[n].x, 0.f); a1[n].y = fmaxf(a1[n].y, 0.f);
            a1[n].z = fmaxf(a1[n].z, 0.f); a1[n].w = fmaxf(a1[n].w, 0.f);
            tr4[(q*4+n)*32 + jq] = a1[n];
        }
        __syncthreads();

        float4 a2[4];
        matvec128(a2, tr4, (const float4*)W2s, b2v, q, jq);

        float4 hv[4];
#pragma unroll
        for (int n = 0; n < 4; n++) {
            float4 v = a2[n];
            v.x = fmaxf(v.x, 0.f); v.y = fmaxf(v.y, 0.f);
            v.z = fmaxf(v.z, 0.f); v.w = fmaxf(v.w, 0.f);
            float s  = v.x + v.y + v.z + v.w;
            float ss = v.x*v.x + v.y*v.y + v.z*v.z + v.w*v.w;
#pragma unroll
            for (int o = 16; o; o >>= 1) {
                s  += __shfl_xor_sync(0xffffffffu, s,  o);
                ss += __shfl_xor_sync(0xffffffffu, ss, o);
            }
            float mu  = s * (1.f/128.f);
            float var = ss * (1.f/128.f) - mu*mu;
            float rs  = rsqrtf(var + LN_EPS);
            int node = nb + q*4 + n;
            float4 xr = __ldg(&((const float4*)x)[(size_t)node*32 + jq]);
            float4 h;
            h.x = (v.x-mu)*rs*g1v.x + e1v.x + xr.x;
            h.y = (v.y-mu)*rs*g1v.y + e1v.y + xr.y;
            h.z = (v.z-mu)*rs*g1v.z + e1v.z + xr.z;
            h.w = (v.w-mu)*rs*g1v.w + e1v.w + xr.w;
            ((float4*)g_h)[(size_t)node*32 + jq] = h;
            hv[n] = h;
        }
        __syncthreads();
#pragma unroll
        for (int n = 0; n < 4; n++) xr4[(q*4+n)*32 + jq] = hv[n];
        __syncthreads();

        float4 a3[4];
        matvec128(a3, xr4, (const float4*)Wgs, zero, q, jq);

        float ps[4], pd[4];
#pragma unroll
        for (int n = 0; n < 4; n++) {
            int node = nb + q*4 + n;
            ((float4*)g_xp)[(size_t)node*32 + jq] = a3[n];
            ps[n] = a3[n].x*asv.x + a3[n].y*asv.y + a3[n].z*asv.z + a3[n].w*asv.w;
            pd[n] = a3[n].x*adv.x + a3[n].y*adv.y + a3[n].z*adv.z + a3[n].w*adv.w;
        }
#pragma unroll
        for (int o = 4; o; o >>= 1) {
#pragma unroll
            for (int n = 0; n < 4; n++) {
                ps[n] += __shfl_down_sync(0xffffffffu, ps[n], o);
                pd[n] += __shfl_down_sync(0xffffffffu, pd[n], o);
            }
        }
        if ((jq & 7) == 0) {
            int head = jq >> 3;
#pragma unroll
            for (int n = 0; n < 4; n++) {
                int node = nb + q*4 + n;
                g_asrc[node*4 + head] = ps[n];
                g_adst[node*4 + head] = pd[n];
            }
        }
        __syncthreads();
    }
}

// ---------------- K3: fused GAT online-softmax gather + LN2 + residual ----------------
__global__ void __launch_bounds__(256) k_gat_g(const float* __restrict__ gatb,
                                               const float* __restrict__ g2,
                                               const float* __restrict__ b2l,
                                               float* __restrict__ out) {
    int node = blockIdx.x * 8 + (threadIdx.x >> 5);
    if (node >= NN) return;
    int lane = threadIdx.x & 31, head = lane >> 3;
    int i = g_off[node], end = g_off[node + 1];

    float adst = g_adst[node*4 + head];
    float m = lrelu(g_asrc[node*4 + head] + adst);     // self-loop logit
    float sum = 1.0f;                                   // exp(self - m) = 1
    float4 acc = ((const float4*)g_xp)[(size_t)node*32 + lane];

    int s = 0;
    if (i < end) s = __ldg(&g_csrs[i]);
    while (i < end) {
        int in = i + 1, sn = 0;
        if (in < end) sn = __ldg(&g_csrs[in]);
        float lg = lrelu(__ldg(&g_asrc[s*4 + head]) + adst);
        float4 xs = __ldg(&((const float4*)g_xp)[(size_t)s*32 + lane]);
        float ev;
        if (lg > m) {
            float sc = __expf(m - lg);
            sum *= sc;
            acc.x *= sc; acc.y *= sc; acc.z *= sc; acc.w *= sc;
            m = lg; ev = 1.0f;
        } else {
            ev = __expf(lg - m);
        }
        sum += ev;
        acc.x = fmaf(ev, xs.x, acc.x);
        acc.y = fmaf(ev, xs.y, acc.y);
        acc.z = fmaf(ev, xs.z, acc.z);
        acc.w = fmaf(ev, xs.w, acc.w);
        s = sn; i = in;
    }

    float inv = 1.0f / (sum + 1e-16f);
    float4 bb = __ldg(&((const float4*)gatb)[lane]);
    float4 v;
    v.x = fmaxf(fmaf(acc.x, inv, bb.x), 0.f);
    v.y = fmaxf(fmaf(acc.y, inv, bb.y), 0.f);
    v.z = fmaxf(fmaf(acc.z, inv, bb.z), 0.f);
    v.w = fmaxf(fmaf(acc.w, inv, bb.w), 0.f);
    float sv  = v.x + v.y + v.z + v.w;
    float ssv = v.x*v.x + v.y*v.y + v.z*v.z + v.w*v.w;
#pragma unroll
    for (int o = 16; o; o >>= 1) {
        sv  += __shfl_xor_sync(0xffffffffu, sv,  o);
        ssv += __shfl_xor_sync(0xffffffffu, ssv, o);
    }
    float mu  = sv * (1.f/128.f);
    float var = ssv * (1.f/128.f) - mu*mu;
    float rs  = rsqrtf(var + LN_EPS);
    float4 gv = __ldg(&((const float4*)g2)[lane]);
    float4 bv = __ldg(&((const float4*)b2l)[lane]);
    float4 hh = ((const float4*)g_h)[(size_t)node*32 + lane];
    float4 r;
    r.x = (v.x-mu)*rs*gv.x + bv.x + hh.x;
    r.y = (v.y-mu)*rs*gv.y + bv.y + hh.y;
    r.z = (v.z-mu)*rs*gv.z + bv.z + hh.z;
    r.w = (v.w-mu)*rs*gv.w + bv.w + hh.w;
    ((float4*)out)[(size_t)node*32 + lane] = r;
}

// ---------------- launch ----------------
extern "C" void kernel_launch(void* const* d_in, const int* in_sizes, int n_in,
                              void* d_out, int out_size) {
    const float* x   = (const float*)d_in[0];
    const int*   ei  = (const int*)  d_in[1];
    const float* ea  = (const float*)d_in[2];
    const float* eps = (const float*)d_in[3];
    const float* w1  = (const float*)d_in[4];
    const float* b1  = (const float*)d_in[5];
    const float* w2  = (const float*)d_in[6];
    const float* b2  = (const float*)d_in[7];
    const float* l1g = (const float*)d_in[8];
    const float* l1b = (const float*)d_in[9];
    const float* gw  = (const float*)d_in[10];
    const float* ats = (const float*)d_in[11];
    const float* atd = (const float*)d_in[12];
    const float* gb  = (const float*)d_in[13];
    const float* l2g = (const float*)d_in[14];
    const float* l2b = (const float*)d_in[15];
    float* out = (float*)d_out;

    cudaFuncSetAttribute(k_mlp, cudaFuncAttributeMaxDynamicSharedMemorySize, 229376);

    // CSR build (by dst)
    k_zero <<<(NN + 255)/256, 256>>>();
    k_hist <<<(EE + 255)/256, 256>>>(ei);
    k_scan1<<<SCAN_BLKS, SCAN_T>>>();
    k_scan2<<<1, 256>>>();
    k_scan3<<<(NN + 255)/256, 256>>>();
    k_fill <<<(EE + 255)/256, 256>>>(ei);

    // main pipeline (gather-based, atomic-free)
    k_gine_g<<<(NN + 7)/8, 256>>>(x, ea, eps);
    k_mlp   <<<152, 256, 229376>>>(x, w1, b1, w2, b2, l1g, l1b, gw, ats, atd);
    k_gat_g <<<(NN + 7)/8, 256>>>(gb, l2g, l2b, out);
}